// round 2
// baseline (speedup 1.0000x reference)
#include <cuda_runtime.h>
#include <math.h>

// Problem constants (ContTimeLSTM_66623532695635)
#define Bsz 128
#define Lseq 512
#define Iin 256
#define Dh 512
#define ND 3584          // 7*D
#define FIN 768          // I + D
#define BD (Bsz*Dh)      // 65536

#define GRID 128         // persistent kernel blocks (<=148 SMs -> co-resident)
#define NTH 256

// ---------------- device scratch ----------------
// XP layout: [t][b][n]
__device__ float g_xp[(size_t)Lseq * Bsz * ND];    // ~940 MB
__device__ float g_H[BD];
__device__ float g_proj0[ND];
__device__ unsigned g_bar;

__device__ __forceinline__ float sigf(float x) { return 1.0f / (1.0f + expf(-x)); }
__device__ __forceinline__ float softplusf(float x) {
    return (x > 0.0f) ? (x + log1pf(expf(-x))) : log1pf(expf(x));
}

__device__ __forceinline__ unsigned ld_acq(unsigned* p) {
    unsigned v;
    asm volatile("ld.acquire.gpu.u32 %0, [%1];" : "=r"(v) : "l"(p) : "memory");
    return v;
}
__device__ __forceinline__ void red_rel_add1(unsigned* p) {
    asm volatile("red.release.gpu.global.add.u32 [%0], 1;" :: "l"(p) : "memory");
}

__global__ void reset_bar_kernel() { g_bar = 0u; }

// ---------------- init: proj0 = bos @ Wx^T + b ----------------
__global__ void init_proj_kernel(const float* __restrict__ bos,
                                 const float* __restrict__ W,
                                 const float* __restrict__ bias) {
    int n = blockIdx.x * blockDim.x + threadIdx.x;
    if (n >= ND) return;
    const float* wrow = W + (size_t)n * FIN;
    float acc = bias[n];
    #pragma unroll 8
    for (int i = 0; i < Iin; i++) acc += bos[i] * wrow[i];
    g_proj0[n] = acc;
}

// ---------------- XP = mask(x) @ Wx^T + bias  (M=65536, K=256, N=3584) ----------------
__global__ __launch_bounds__(256, 2)
void xproj_gemm_kernel(const float* __restrict__ x,
                       const float* __restrict__ W,
                       const float* __restrict__ bias,
                       const int* __restrict__ seq_lens) {
    __shared__ float As[16][65];
    __shared__ float Bs[16][65];
    int tid = threadIdx.x;
    int tx = tid & 15;
    int ty = tid >> 4;
    int m0 = blockIdx.y * 64;
    int n0 = blockIdx.x * 64;

    float acc[4][4];
    #pragma unroll
    for (int i = 0; i < 4; i++)
        #pragma unroll
        for (int j = 0; j < 4; j++) acc[i][j] = 0.0f;

    for (int k0 = 0; k0 < Iin; k0 += 16) {
        #pragma unroll
        for (int it = 0; it < 4; it++) {
            int idx = tid + it * 256;
            int c = idx & 15;
            int r = idx >> 4;
            int row = m0 + r;
            int t = row >> 7;
            int b = row & 127;
            float v = 0.0f;
            if (t < seq_lens[b]) v = x[((size_t)b * Lseq + t) * Iin + k0 + c];
            As[c][r] = v;
        }
        #pragma unroll
        for (int it = 0; it < 4; it++) {
            int idx = tid + it * 256;
            int c = idx & 15;
            int r = idx >> 4;
            Bs[c][r] = W[(size_t)(n0 + r) * FIN + k0 + c];
        }
        __syncthreads();
        #pragma unroll
        for (int kk = 0; kk < 16; kk++) {
            float a[4], bb[4];
            #pragma unroll
            for (int i = 0; i < 4; i++) a[i] = As[kk][ty * 4 + i];
            #pragma unroll
            for (int j = 0; j < 4; j++) bb[j] = Bs[kk][tx * 4 + j];
            #pragma unroll
            for (int i = 0; i < 4; i++)
                #pragma unroll
                for (int j = 0; j < 4; j++) acc[i][j] += a[i] * bb[j];
        }
        __syncthreads();
    }
    #pragma unroll
    for (int i = 0; i < 4; i++) {
        int row = m0 + ty * 4 + i;
        #pragma unroll
        for (int j = 0; j < 4; j++) {
            int n = n0 + tx * 4 + j;
            g_xp[(size_t)row * ND + n] = acc[i][j] + bias[n];
        }
    }
}

// ---------------- persistent recurrence kernel ----------------
// Grid 128 = 2 (b-halves) x 64 (d-chunks of 8). Each block owns, for its
// 64 b's and 8 d's, all 7 gate columns: GEMM tile 64b x 56n, state update local.
__global__ __launch_bounds__(NTH, 1)
void recur_kernel(const float* __restrict__ W,
                  const float* __restrict__ dt,
                  const int* __restrict__ sl,
                  float* __restrict__ out_h,
                  float* __restrict__ out_final) {
    const int tid = threadIdx.x;
    const int bm = blockIdx.x >> 6;    // 0..1
    const int dn = blockIdx.x & 63;    // 0..63
    const int tx = tid & 15;           // n micro (only tx<14 active in compute)
    const int ty = tid >> 4;           // b micro

    __shared__ float As[16][68];       // [k][b], 272B rows (16B aligned)
    __shared__ float Bs[16][64];       // [k][n], extra width = safe garbage for tx>=14
    __shared__ float Pj[64][57];       // proj tile [b_local][gate*8+j]

    // ---- per-thread recurrent state: 2 elements, e = tid + i*256 ----
    float stC[2], stCe[2];
    int eb[2], ed[2], elen[2];
    #pragma unroll
    for (int i = 0; i < 2; i++) {
        int e = tid + i * NTH;
        int bl = e >> 3, j = e & 7;
        int b = bm * 64 + bl;
        int d = dn * 8 + j;
        eb[i] = b; ed[i] = d; elen[i] = sl[b];
        float p0 = g_proj0[0 * Dh + d];
        float p2 = g_proj0[2 * Dh + d];
        float p4 = g_proj0[4 * Dh + d];
        float p5 = g_proj0[5 * Dh + d];
        float p6 = g_proj0[6 * Dh + d];
        float z   = tanhf(p5);
        float cs0 = sigf(p0) * z;
        float ce0 = sigf(p2) * z;
        float o0  = sigf(p4);
        float dn0 = softplusf(p6);
        float dtv = dt[b * Lseq + 0];
        float c = ce0 + (cs0 - ce0) * expf(-dn0 * dtv);
        float h = o0 * tanhf(c);
        stC[i] = c; stCe[i] = ce0;
        g_H[b * Dh + d] = h;
        out_h[((size_t)b * Lseq + 0) * Dh + d] = h;
    }

    // precompute W row pointers' n indices for B-tile loads
    // B tile row r (0..55): n = (r>>3)*Dh + dn*8 + (r&7)

    // grid barrier after init (h_0 visible to all)
    unsigned tgt = GRID;
    {
        __syncthreads();
        if (tid == 0) {
            red_rel_add1(&g_bar);
            while (ld_acq(&g_bar) < tgt) {}
        }
        __syncthreads();
    }

    for (int t = 0; t < Lseq; t++) {
        float acc[4][4];
        #pragma unroll
        for (int i = 0; i < 4; i++)
            #pragma unroll
            for (int j = 0; j < 4; j++) acc[i][j] = 0.0f;

        // stage k0=0
        float pa[4], pb[4];
        #pragma unroll
        for (int it = 0; it < 4; it++) {
            int idx = tid + it * 256;
            pa[it] = g_H[(bm * 64 + (idx >> 4)) * Dh + (idx & 15)];
        }
        #pragma unroll
        for (int it = 0; it < 4; it++) {
            int idx = tid + it * 256;
            if (idx < 896) {
                int r = idx >> 4;
                int n = (r >> 3) * Dh + dn * 8 + (r & 7);
                pb[it] = W[(size_t)n * FIN + Iin + (idx & 15)];
            }
        }

        for (int k0 = 0; k0 < Dh; k0 += 16) {
            __syncthreads();   // previous tile consumed / Pj reads done
            #pragma unroll
            for (int it = 0; it < 4; it++) {
                int idx = tid + it * 256;
                As[idx & 15][idx >> 4] = pa[it];
            }
            #pragma unroll
            for (int it = 0; it < 4; it++) {
                int idx = tid + it * 256;
                if (idx < 896) Bs[idx & 15][idx >> 4] = pb[it];
            }
            __syncthreads();
            // prefetch next tile (latency overlaps compute)
            if (k0 + 16 < Dh) {
                #pragma unroll
                for (int it = 0; it < 4; it++) {
                    int idx = tid + it * 256;
                    pa[it] = g_H[(bm * 64 + (idx >> 4)) * Dh + k0 + 16 + (idx & 15)];
                }
                #pragma unroll
                for (int it = 0; it < 4; it++) {
                    int idx = tid + it * 256;
                    if (idx < 896) {
                        int r = idx >> 4;
                        int n = (r >> 3) * Dh + dn * 8 + (r & 7);
                        pb[it] = W[(size_t)n * FIN + Iin + k0 + 16 + (idx & 15)];
                    }
                }
            }
            #pragma unroll
            for (int kk = 0; kk < 16; kk++) {
                float4 av = *(const float4*)&As[kk][ty * 4];
                float4 bv = *(const float4*)&Bs[kk][tx * 4];
                float a[4] = {av.x, av.y, av.z, av.w};
                float b4[4] = {bv.x, bv.y, bv.z, bv.w};
                #pragma unroll
                for (int i = 0; i < 4; i++)
                    #pragma unroll
                    for (int j = 0; j < 4; j++) acc[i][j] += a[i] * b4[j];
            }
        }

        // epilogue: Pj = acc + XP[t]
        __syncthreads();
        if (tx < 14) {
            int g = tx >> 1;
            int joff = (tx & 1) * 4;
            const float* xpt = g_xp + ((size_t)t * Bsz + bm * 64) * ND;
            #pragma unroll
            for (int i = 0; i < 4; i++) {
                int bl = ty * 4 + i;
                float4 xv = *(const float4*)&xpt[(size_t)bl * ND + g * Dh + dn * 8 + joff];
                Pj[bl][tx * 4 + 0] = acc[i][0] + xv.x;
                Pj[bl][tx * 4 + 1] = acc[i][1] + xv.y;
                Pj[bl][tx * 4 + 2] = acc[i][2] + xv.z;
                Pj[bl][tx * 4 + 3] = acc[i][3] + xv.w;
            }
        }
        __syncthreads();

        // state update (block-local)
        #pragma unroll
        for (int i = 0; i < 2; i++) {
            int e = tid + i * NTH;
            int bl = e >> 3, j = e & 7;
            float i_g  = sigf(Pj[bl][0 * 8 + j]);
            float f_g  = sigf(Pj[bl][1 * 8 + j]);
            float ie_g = sigf(Pj[bl][2 * 8 + j]);
            float fe_g = sigf(Pj[bl][3 * 8 + j]);
            float o_n  = sigf(Pj[bl][4 * 8 + j]);
            float z    = tanhf(Pj[bl][5 * 8 + j]);
            float d_n  = softplusf(Pj[bl][6 * 8 + j]);
            float cs_n = f_g * stC[i] + i_g * z;
            float ce_n = fe_g * stCe[i] + ie_g * z;
            int b = eb[i], d = ed[i], len = elen[i];
            if (t == len - 1) {
                float* f = out_final + (size_t)b * 4 * Dh;
                f[0 * Dh + d] = o_n;
                f[1 * Dh + d] = cs_n;
                f[2 * Dh + d] = ce_n;
                f[3 * Dh + d] = d_n;
            }
            if (t + 1 < Lseq) {
                float dtv = ((t + 1) < len) ? dt[b * Lseq + t + 1] : 0.0f;
                float cn = ce_n + (cs_n - ce_n) * expf(-d_n * dtv);
                float h = o_n * tanhf(cn);
                stC[i] = cn; stCe[i] = ce_n;
                g_H[b * Dh + d] = h;
                out_h[((size_t)b * Lseq + (t + 1)) * Dh + d] = h;
            }
        }

        // grid barrier: h_{t+1} visible before next GEMM (skip after last step)
        if (t + 1 < Lseq) {
            tgt += GRID;
            __syncthreads();
            if (tid == 0) {
                red_rel_add1(&g_bar);
                while (ld_acq(&g_bar) < tgt) {}
            }
            __syncthreads();
        }
    }
}

// ---------------- launch ----------------
extern "C" void kernel_launch(void* const* d_in, const int* in_sizes, int n_in,
                              void* d_out, int out_size) {
    const float* x    = (const float*)d_in[0];   // (B,L,I)
    const float* dt   = (const float*)d_in[1];   // (B,L)
    const int*   sl   = (const int*)  d_in[2];   // (B,)
    const float* bos  = (const float*)d_in[3];   // (I,)
    const float* W    = (const float*)d_in[4];   // (7D, I+D)
    const float* bias = (const float*)d_in[5];   // (7D,)
    float* out = (float*)d_out;
    float* out_final = out + (size_t)Bsz * Lseq * Dh;

    reset_bar_kernel<<<1, 1>>>();
    init_proj_kernel<<<(ND + 255) / 256, 256>>>(bos, W, bias);
    xproj_gemm_kernel<<<dim3(ND / 64, (Bsz * Lseq) / 64), 256>>>(x, W, bias, sl);
    recur_kernel<<<GRID, NTH>>>(W, dt, sl, out, out_final);
}

// round 4
// speedup vs baseline: 1.5931x; 1.5931x over previous
#include <cuda_runtime.h>
#include <cuda_bf16.h>
#include <math.h>
#include <stdint.h>

// Problem constants (ContTimeLSTM_66623532695635)
#define Bsz 128
#define Lseq 512
#define Iin 256
#define Dh 512
#define ND 3584          // 7*D
#define FIN 768          // I + D
#define BD (Bsz*Dh)      // 65536

#define GRID_R 64        // persistent recur blocks (<=148 SMs -> co-resident)
#define NTR 128          // 4 warps

// ---------------- device scratch ----------------
__device__ float g_xp[(size_t)Lseq * Bsz * ND];    // ~940 MB, [t][b][n]
__device__ uint32_t g_Hsplit[2][BD];               // packed bf16 (hi | lo<<16), double-buffered
__device__ float g_proj0[ND];
__device__ unsigned g_bar;

__device__ __forceinline__ float sigf(float x) { return 1.0f / (1.0f + expf(-x)); }
__device__ __forceinline__ float softplusf(float x) {
    return (x > 0.0f) ? (x + log1pf(expf(-x))) : log1pf(expf(x));
}

__device__ __forceinline__ unsigned ld_acq(unsigned* p) {
    unsigned v;
    asm volatile("ld.acquire.gpu.u32 %0, [%1];" : "=r"(v) : "l"(p) : "memory");
    return v;
}
__device__ __forceinline__ void red_rel_add1(unsigned* p) {
    asm volatile("red.release.gpu.global.add.u32 [%0], 1;" :: "l"(p) : "memory");
}
__device__ __forceinline__ uint32_t prmt_(uint32_t a, uint32_t b, uint32_t s) {
    uint32_t r;
    asm("prmt.b32 %0, %1, %2, %3;" : "=r"(r) : "r"(a), "r"(b), "r"(s));
    return r;
}
__device__ __forceinline__ uint32_t pack_hl(float v) {
    __nv_bfloat16 hi = __float2bfloat16(v);
    __nv_bfloat16 lo = __float2bfloat16(v - __bfloat162float(hi));
    return ((uint32_t)__bfloat16_as_ushort(lo) << 16) | __bfloat16_as_ushort(hi);
}
__device__ __forceinline__ uint32_t pack2bf(__nv_bfloat16 a, __nv_bfloat16 b) {
    return ((uint32_t)__bfloat16_as_ushort(b) << 16) | __bfloat16_as_ushort(a);
}

#define MMA_BF16(d, a, b0, b1) \
    asm volatile("mma.sync.aligned.m16n8k16.row.col.f32.bf16.bf16.f32 " \
        "{%0,%1,%2,%3}, {%4,%5,%6,%7}, {%8,%9}, {%0,%1,%2,%3};" \
        : "+f"((d)[0]), "+f"((d)[1]), "+f"((d)[2]), "+f"((d)[3]) \
        : "r"((a)[0]), "r"((a)[1]), "r"((a)[2]), "r"((a)[3]), "r"(b0), "r"(b1))

__global__ void reset_bar_kernel() { g_bar = 0u; }

// ---------------- init: proj0 = bos @ Wx^T + b ----------------
__global__ void init_proj_kernel(const float* __restrict__ bos,
                                 const float* __restrict__ W,
                                 const float* __restrict__ bias) {
    int n = blockIdx.x * blockDim.x + threadIdx.x;
    if (n >= ND) return;
    const float* wrow = W + (size_t)n * FIN;
    float acc = bias[n];
    #pragma unroll 8
    for (int i = 0; i < Iin; i++) acc += bos[i] * wrow[i];
    g_proj0[n] = acc;
}

// ---------------- XP = mask(x) @ Wx^T + bias  (M=65536, K=256, N=3584) ----------------
__global__ __launch_bounds__(256, 2)
void xproj_gemm_kernel(const float* __restrict__ x,
                       const float* __restrict__ W,
                       const float* __restrict__ bias,
                       const int* __restrict__ seq_lens) {
    __shared__ float As[16][65];
    __shared__ float Bs[16][65];
    int tid = threadIdx.x;
    int tx = tid & 15;
    int ty = tid >> 4;
    int m0 = blockIdx.y * 64;
    int n0 = blockIdx.x * 64;

    float acc[4][4];
    #pragma unroll
    for (int i = 0; i < 4; i++)
        #pragma unroll
        for (int j = 0; j < 4; j++) acc[i][j] = 0.0f;

    for (int k0 = 0; k0 < Iin; k0 += 16) {
        #pragma unroll
        for (int it = 0; it < 4; it++) {
            int idx = tid + it * 256;
            int c = idx & 15;
            int r = idx >> 4;
            int row = m0 + r;
            int t = row >> 7;
            int b = row & 127;
            float v = 0.0f;
            if (t < seq_lens[b]) v = x[((size_t)b * Lseq + t) * Iin + k0 + c];
            As[c][r] = v;
        }
        #pragma unroll
        for (int it = 0; it < 4; it++) {
            int idx = tid + it * 256;
            int c = idx & 15;
            int r = idx >> 4;
            Bs[c][r] = W[(size_t)(n0 + r) * FIN + k0 + c];
        }
        __syncthreads();
        #pragma unroll
        for (int kk = 0; kk < 16; kk++) {
            float a[4], bb[4];
            #pragma unroll
            for (int i = 0; i < 4; i++) a[i] = As[kk][ty * 4 + i];
            #pragma unroll
            for (int j = 0; j < 4; j++) bb[j] = Bs[kk][tx * 4 + j];
            #pragma unroll
            for (int i = 0; i < 4; i++)
                #pragma unroll
                for (int j = 0; j < 4; j++) acc[i][j] += a[i] * bb[j];
        }
        __syncthreads();
    }
    #pragma unroll
    for (int i = 0; i < 4; i++) {
        int row = m0 + ty * 4 + i;
        #pragma unroll
        for (int j = 0; j < 4; j++) {
            int n = n0 + tx * 4 + j;
            g_xp[(size_t)row * ND + n] = acc[i][j] + bias[n];
        }
    }
}

// ================= persistent mma.sync recurrence =================
// 64 blocks; block dn owns d-slice [dn*8, dn*8+8) x 7 gates -> N=56.
// Warp w owns batch rows [w*32, w*32+32) (M=32 -> 2 m-tiles of 16).
// W slice pre-split (bf16 hi/lo) and pre-packed in fragment-linear smem layout.
// 3-pass split GEMM per k-step: hi*Whi + lo*Whi + hi*Wlo.
#define NFRAG 224                 // 32 k-steps * 7 n-tiles
#define PLANE (NFRAG * 64)        // u32 per plane

__global__ __launch_bounds__(NTR, 1)
void recur_kernel(const float* __restrict__ W,
                  const float* __restrict__ dt,
                  const int* __restrict__ sl,
                  float* __restrict__ out_h,
                  float* __restrict__ out_final) {
    extern __shared__ uint32_t sB[];     // [2][NFRAG][32][2] u32

    const int tid = threadIdx.x;
    const int w = tid >> 5;
    const int lane = tid & 31;
    const int g = lane >> 2;
    const int tq = lane & 3;
    const int dn = blockIdx.x;           // 0..63
    const int d0 = dn * 8 + tq * 2;      // this lane's d pair: d0, d0+1

    // ---- pack W fragments into smem (one time) ----
    for (int e = tid; e < NFRAG * 32; e += NTR) {
        int f = e >> 5;                  // frag id = ks*7 + nt
        int l = e & 31;
        int ks = f / 7, nt = f % 7;
        int gg = l >> 2, tt = l & 3;
        int n = nt * Dh + dn * 8 + gg;   // W row
        const float* wr = W + (size_t)n * FIN + Iin + ks * 16;
        float w0 = wr[tt * 2], w1 = wr[tt * 2 + 1];
        float w2 = wr[tt * 2 + 8], w3 = wr[tt * 2 + 9];
        __nv_bfloat16 h0 = __float2bfloat16(w0), h1 = __float2bfloat16(w1);
        __nv_bfloat16 h2 = __float2bfloat16(w2), h3 = __float2bfloat16(w3);
        __nv_bfloat16 l0 = __float2bfloat16(w0 - __bfloat162float(h0));
        __nv_bfloat16 l1 = __float2bfloat16(w1 - __bfloat162float(h1));
        __nv_bfloat16 l2 = __float2bfloat16(w2 - __bfloat162float(h2));
        __nv_bfloat16 l3 = __float2bfloat16(w3 - __bfloat162float(h3));
        sB[(f * 32 + l) * 2 + 0] = pack2bf(h0, h1);
        sB[(f * 32 + l) * 2 + 1] = pack2bf(h2, h3);
        sB[PLANE + (f * 32 + l) * 2 + 0] = pack2bf(l0, l1);
        sB[PLANE + (f * 32 + l) * 2 + 1] = pack2bf(l2, l3);
    }

    // ---- lane's (b,d) ownership: b = w*32 + mt*16 + rh*8 + g ----
    int bsr[2][2], lenr[2][2];
    #pragma unroll
    for (int mt = 0; mt < 2; mt++)
        #pragma unroll
        for (int rh = 0; rh < 2; rh++) {
            bsr[mt][rh] = w * 32 + mt * 16 + rh * 8 + g;
            lenr[mt][rh] = sl[bsr[mt][rh]];
        }

    // ---- init state t=0 ----
    float stC[2][2][2], stCe[2][2][2];
    #pragma unroll
    for (int mt = 0; mt < 2; mt++)
        #pragma unroll
        for (int rh = 0; rh < 2; rh++) {
            int b = bsr[mt][rh];
            float dtv = dt[b * Lseq + 0];
            float h2v[2];
            uint32_t hp[2];
            #pragma unroll
            for (int cj = 0; cj < 2; cj++) {
                int d = d0 + cj;
                float p0 = g_proj0[0 * Dh + d];
                float p2 = g_proj0[2 * Dh + d];
                float p4 = g_proj0[4 * Dh + d];
                float p5 = g_proj0[5 * Dh + d];
                float p6 = g_proj0[6 * Dh + d];
                float z   = tanhf(p5);
                float cs0 = sigf(p0) * z;
                float ce0 = sigf(p2) * z;
                float o0  = sigf(p4);
                float dn0 = softplusf(p6);
                float c = ce0 + (cs0 - ce0) * expf(-dn0 * dtv);
                float h = o0 * tanhf(c);
                stC[mt][rh][cj] = c;
                stCe[mt][rh][cj] = ce0;
                h2v[cj] = h;
                hp[cj] = pack_hl(h);
            }
            *(float2*)&out_h[((size_t)b * Lseq + 0) * Dh + d0] = make_float2(h2v[0], h2v[1]);
            *(uint2*)&g_Hsplit[0][b * Dh + d0] = make_uint2(hp[0], hp[1]);
        }

    // grid barrier (h_0 + smem pack visible)
    unsigned tgt = GRID_R;
    {
        __syncthreads();
        if (tid == 0) {
            red_rel_add1(&g_bar);
            while (ld_acq(&g_bar) < tgt) {}
        }
        __syncthreads();
    }

    for (int t = 0; t < Lseq; t++) {
        const uint32_t* Hs = g_Hsplit[t & 1];
        const float* xpt = g_xp + (size_t)t * Bsz * ND;

        // ---- acc init = XP slice ----
        float acc[2][7][4];
        #pragma unroll
        for (int mt = 0; mt < 2; mt++) {
            const float* pb0 = xpt + (size_t)bsr[mt][0] * ND + d0;
            const float* pb1 = xpt + (size_t)bsr[mt][1] * ND + d0;
            #pragma unroll
            for (int nt = 0; nt < 7; nt++) {
                float2 x0 = *(const float2*)(pb0 + nt * Dh);
                float2 x1 = *(const float2*)(pb1 + nt * Dh);
                acc[mt][nt][0] = x0.x; acc[mt][nt][1] = x0.y;
                acc[mt][nt][2] = x1.x; acc[mt][nt][3] = x1.y;
            }
        }

        // ---- A prefetch (ks=0) ----
        uint2 ua[2][4];
        #pragma unroll
        for (int mt = 0; mt < 2; mt++) {
            int r0 = bsr[mt][0], r1 = bsr[mt][1];
            int kb = tq * 2;
            ua[mt][0] = *(const uint2*)(Hs + r0 * Dh + kb);
            ua[mt][1] = *(const uint2*)(Hs + r1 * Dh + kb);
            ua[mt][2] = *(const uint2*)(Hs + r0 * Dh + kb + 8);
            ua[mt][3] = *(const uint2*)(Hs + r1 * Dh + kb + 8);
        }

        #pragma unroll 1
        for (int ks = 0; ks < 32; ks++) {
            // B frags from smem
            uint32_t bh[7][2], bl[7][2];
            #pragma unroll
            for (int nt = 0; nt < 7; nt++) {
                const uint32_t* sp = sB + ((ks * 7 + nt) * 32 + lane) * 2;
                uint2 vh = *(const uint2*)sp;
                uint2 vl = *(const uint2*)(sp + PLANE);
                bh[nt][0] = vh.x; bh[nt][1] = vh.y;
                bl[nt][0] = vl.x; bl[nt][1] = vl.y;
            }
            // unpack A
            uint32_t ah[2][4], al[2][4];
            #pragma unroll
            for (int mt = 0; mt < 2; mt++)
                #pragma unroll
                for (int q = 0; q < 4; q++) {
                    ah[mt][q] = prmt_(ua[mt][q].x, ua[mt][q].y, 0x5410);
                    al[mt][q] = prmt_(ua[mt][q].x, ua[mt][q].y, 0x7632);
                }
            // prefetch next A (consumed next iter; hidden behind MMAs)
            if (ks + 1 < 32) {
                int kb = (ks + 1) * 16 + tq * 2;
                #pragma unroll
                for (int mt = 0; mt < 2; mt++) {
                    int r0 = bsr[mt][0], r1 = bsr[mt][1];
                    ua[mt][0] = *(const uint2*)(Hs + r0 * Dh + kb);
                    ua[mt][1] = *(const uint2*)(Hs + r1 * Dh + kb);
                    ua[mt][2] = *(const uint2*)(Hs + r0 * Dh + kb + 8);
                    ua[mt][3] = *(const uint2*)(Hs + r1 * Dh + kb + 8);
                }
            }
            // 42 MMAs
            #pragma unroll
            for (int mt = 0; mt < 2; mt++)
                #pragma unroll
                for (int nt = 0; nt < 7; nt++) {
                    MMA_BF16(acc[mt][nt], ah[mt], bh[nt][0], bh[nt][1]);
                    MMA_BF16(acc[mt][nt], al[mt], bh[nt][0], bh[nt][1]);
                    MMA_BF16(acc[mt][nt], ah[mt], bl[nt][0], bl[nt][1]);
                }
        }

        // ---- epilogue: gates + state, all in-register ----
        #pragma unroll
        for (int mt = 0; mt < 2; mt++)
            #pragma unroll
            for (int rh = 0; rh < 2; rh++) {
                int b = bsr[mt][rh];
                int len = lenr[mt][rh];
                float dtv = 0.0f;
                if (t + 1 < Lseq) dtv = ((t + 1) < len) ? dt[b * Lseq + t + 1] : 0.0f;
                float hn[2];
                uint32_t hp[2];
                #pragma unroll
                for (int cj = 0; cj < 2; cj++) {
                    int ci = rh * 2 + cj;
                    float i_g  = sigf(acc[mt][0][ci]);
                    float f_g  = sigf(acc[mt][1][ci]);
                    float ie_g = sigf(acc[mt][2][ci]);
                    float fe_g = sigf(acc[mt][3][ci]);
                    float o_n  = sigf(acc[mt][4][ci]);
                    float z    = tanhf(acc[mt][5][ci]);
                    float d_n  = softplusf(acc[mt][6][ci]);
                    float cs_n = f_g * stC[mt][rh][cj] + i_g * z;
                    float ce_n = fe_g * stCe[mt][rh][cj] + ie_g * z;
                    if (t == len - 1) {
                        float* f = out_final + (size_t)b * 4 * Dh + d0 + cj;
                        f[0 * Dh] = o_n;
                        f[1 * Dh] = cs_n;
                        f[2 * Dh] = ce_n;
                        f[3 * Dh] = d_n;
                    }
                    float cn = ce_n + (cs_n - ce_n) * expf(-d_n * dtv);
                    float h = o_n * tanhf(cn);
                    stC[mt][rh][cj] = cn;
                    stCe[mt][rh][cj] = ce_n;
                    hn[cj] = h;
                    hp[cj] = pack_hl(h);
                }
                if (t + 1 < Lseq) {
                    *(float2*)&out_h[((size_t)b * Lseq + (t + 1)) * Dh + d0] =
                        make_float2(hn[0], hn[1]);
                    *(uint2*)&g_Hsplit[(t + 1) & 1][b * Dh + d0] = make_uint2(hp[0], hp[1]);
                }
            }

        // grid barrier: h_{t+1} visible before next step's A loads
        if (t + 1 < Lseq) {
            tgt += GRID_R;
            __syncthreads();
            if (tid == 0) {
                red_rel_add1(&g_bar);
                while (ld_acq(&g_bar) < tgt) {}
            }
            __syncthreads();
        }
    }
}

// ---------------- launch ----------------
extern "C" void kernel_launch(void* const* d_in, const int* in_sizes, int n_in,
                              void* d_out, int out_size) {
    const float* x    = (const float*)d_in[0];   // (B,L,I)
    const float* dt   = (const float*)d_in[1];   // (B,L)
    const int*   sl   = (const int*)  d_in[2];   // (B,)
    const float* bos  = (const float*)d_in[3];   // (I,)
    const float* W    = (const float*)d_in[4];   // (7D, I+D)
    const float* bias = (const float*)d_in[5];   // (7D,)
    float* out = (float*)d_out;
    float* out_final = out + (size_t)Bsz * Lseq * Dh;

    cudaFuncSetAttribute(recur_kernel, cudaFuncAttributeMaxDynamicSharedMemorySize,
                         2 * PLANE * 4);

    reset_bar_kernel<<<1, 1>>>();
    init_proj_kernel<<<(ND + 255) / 256, 256>>>(bos, W, bias);
    xproj_gemm_kernel<<<dim3(ND / 64, (Bsz * Lseq) / 64), 256>>>(x, W, bias, sl);
    recur_kernel<<<GRID_R, NTR, 2 * PLANE * 4>>>(W, dt, sl, out, out_final);
}

// round 5
// speedup vs baseline: 3.6105x; 2.2664x over previous
#include <cuda_runtime.h>
#include <cuda_bf16.h>
#include <math.h>
#include <stdint.h>

// Problem constants (ContTimeLSTM_66623532695635)
#define Bsz 128
#define Lseq 512
#define Iin 256
#define Dh 512
#define ND 3584          // 7*D
#define FIN 768          // I + D
#define BD (Bsz*Dh)      // 65536

#define GRID_R 128       // persistent recur blocks (<=148 SMs -> co-resident)
#define NTR 128          // 4 warps

// ---------------- device scratch ----------------
__device__ float g_xp[(size_t)Lseq * Bsz * ND];        // ~940 MB, [t][b][n]
__device__ uint32_t g_Hsplit[2][BD];                   // packed bf16 (hi | lo<<16)
__device__ uint32_t g_xpack[(size_t)Bsz * Lseq * Iin]; // packed masked x, [row=t*128+b][i]
#define WFRAG_PLANE (28 * 16384)
__device__ uint32_t g_wfrag[2 * WFRAG_PLANE];          // W x-part fragments, hi|lo planes
__device__ float g_proj0[ND];
__device__ unsigned g_bar;

__device__ __forceinline__ float sigf(float x) { return 1.0f / (1.0f + expf(-x)); }
__device__ __forceinline__ float softplusf(float x) {
    return (x > 0.0f) ? (x + log1pf(expf(-x))) : log1pf(expf(x));
}
__device__ __forceinline__ unsigned ld_acq(unsigned* p) {
    unsigned v;
    asm volatile("ld.acquire.gpu.u32 %0, [%1];" : "=r"(v) : "l"(p) : "memory");
    return v;
}
__device__ __forceinline__ void red_rel_add1(unsigned* p) {
    asm volatile("red.release.gpu.global.add.u32 [%0], 1;" :: "l"(p) : "memory");
}
__device__ __forceinline__ uint32_t prmt_(uint32_t a, uint32_t b, uint32_t s) {
    uint32_t r;
    asm("prmt.b32 %0, %1, %2, %3;" : "=r"(r) : "r"(a), "r"(b), "r"(s));
    return r;
}
__device__ __forceinline__ uint32_t pack_hl(float v) {
    __nv_bfloat16 hi = __float2bfloat16(v);
    __nv_bfloat16 lo = __float2bfloat16(v - __bfloat162float(hi));
    return ((uint32_t)__bfloat16_as_ushort(lo) << 16) | __bfloat16_as_ushort(hi);
}
__device__ __forceinline__ uint32_t pack2bf(__nv_bfloat16 a, __nv_bfloat16 b) {
    return ((uint32_t)__bfloat16_as_ushort(b) << 16) | __bfloat16_as_ushort(a);
}

#define MMA_BF16(d, a, b0, b1) \
    asm volatile("mma.sync.aligned.m16n8k16.row.col.f32.bf16.bf16.f32 " \
        "{%0,%1,%2,%3}, {%4,%5,%6,%7}, {%8,%9}, {%0,%1,%2,%3};" \
        : "+f"((d)[0]), "+f"((d)[1]), "+f"((d)[2]), "+f"((d)[3]) \
        : "r"((a)[0]), "r"((a)[1]), "r"((a)[2]), "r"((a)[3]), "r"(b0), "r"(b1))

__global__ void reset_bar_kernel() { g_bar = 0u; }

// ---------------- init: proj0 = bos @ Wx^T + b ----------------
__global__ void init_proj_kernel(const float* __restrict__ bos,
                                 const float* __restrict__ W,
                                 const float* __restrict__ bias) {
    int n = blockIdx.x * blockDim.x + threadIdx.x;
    if (n >= ND) return;
    const float* wrow = W + (size_t)n * FIN;
    float acc = bias[n];
    #pragma unroll 8
    for (int i = 0; i < Iin; i++) acc += bos[i] * wrow[i];
    g_proj0[n] = acc;
}

// ---------------- pack masked x into split-bf16 ----------------
__global__ void pack_x_kernel(const float* __restrict__ x,
                              const int* __restrict__ sl) {
    int idx = blockIdx.x * blockDim.x + threadIdx.x;   // < 65536*256
    int row = idx >> 8;
    int i = idx & 255;
    int t = row >> 7;
    int b = row & 127;
    float v = (t < __ldg(sl + b)) ? x[((size_t)b * Lseq + t) * Iin + i] : 0.0f;
    g_xpack[idx] = pack_hl(v);
}

// ---------------- pack W x-part into HMMA B-fragment layout ----------------
// layout: [plane][nb(28)][ks(16)][nt(16)][lane(32)][2]
__global__ void pack_w_kernel(const float* __restrict__ W) {
    int idx = blockIdx.x * blockDim.x + threadIdx.x;   // < 229376
    if (idx >= 28 * 16 * 16 * 32) return;
    int lane = idx & 31;
    int nt = (idx >> 5) & 15;
    int ks = (idx >> 9) & 15;
    int nb = idx >> 13;
    int gg = lane >> 2, tt = lane & 3;
    int n = nb * 128 + nt * 8 + gg;
    const float* wr = W + (size_t)n * FIN + ks * 16 + tt * 2;
    float w0 = wr[0], w1 = wr[1], w2 = wr[8], w3 = wr[9];
    __nv_bfloat16 h0 = __float2bfloat16(w0), h1 = __float2bfloat16(w1);
    __nv_bfloat16 h2 = __float2bfloat16(w2), h3 = __float2bfloat16(w3);
    __nv_bfloat16 l0 = __float2bfloat16(w0 - __bfloat162float(h0));
    __nv_bfloat16 l1 = __float2bfloat16(w1 - __bfloat162float(h1));
    __nv_bfloat16 l2 = __float2bfloat16(w2 - __bfloat162float(h2));
    __nv_bfloat16 l3 = __float2bfloat16(w3 - __bfloat162float(h3));
    size_t base = (size_t)idx * 2;
    g_wfrag[base] = pack2bf(h0, h1);
    g_wfrag[base + 1] = pack2bf(h2, h3);
    g_wfrag[WFRAG_PLANE + base] = pack2bf(l0, l1);
    g_wfrag[WFRAG_PLANE + base + 1] = pack2bf(l2, l3);
}

// ---------------- XP = mask(x) @ Wx^T + bias via HMMA ----------------
// grid (28, 512); block 256 thr / 8 warps; tile M=128 (warp: 16 rows), N=128.
__global__ __launch_bounds__(256, 1)
void xproj_hmma_kernel(const float* __restrict__ bias) {
    extern __shared__ uint32_t sW[];   // [2][16][16][32][2] = 32768 u32 = 128 KB
    const int tid = threadIdx.x;
    const int w = tid >> 5, lane = tid & 31;
    const int g = lane >> 2, tq = lane & 3;
    const int nb = blockIdx.x, mb = blockIdx.y;

    // stage W fragments
    #pragma unroll
    for (int p = 0; p < 2; p++) {
        const uint4* src = (const uint4*)(g_wfrag + (size_t)p * WFRAG_PLANE + nb * 16384);
        uint4* dst = (uint4*)(sW + p * 16384);
        #pragma unroll
        for (int i = 0; i < 16; i++) dst[tid + i * 256] = src[tid + i * 256];
    }
    __syncthreads();

    const int r0 = mb * 128 + w * 16 + g;     // r1 = r0 + 8

    float acc[16][4];
    #pragma unroll
    for (int nt = 0; nt < 16; nt++) {
        int n = nb * 128 + nt * 8 + tq * 2;
        float b0 = __ldg(bias + n), b1 = __ldg(bias + n + 1);
        acc[nt][0] = b0; acc[nt][1] = b1; acc[nt][2] = b0; acc[nt][3] = b1;
    }

    // ring-2 A prefetch
    uint2 ring[2][4];
    #pragma unroll
    for (int p = 0; p < 2; p++) {
        int kb = p * 16 + tq * 2;
        ring[p][0] = *(const uint2*)(g_xpack + (size_t)r0 * Iin + kb);
        ring[p][1] = *(const uint2*)(g_xpack + (size_t)(r0 + 8) * Iin + kb);
        ring[p][2] = *(const uint2*)(g_xpack + (size_t)r0 * Iin + kb + 8);
        ring[p][3] = *(const uint2*)(g_xpack + (size_t)(r0 + 8) * Iin + kb + 8);
    }

    #pragma unroll 2
    for (int ks = 0; ks < 16; ks++) {
        int slot = ks & 1;
        uint32_t ah[4], al[4];
        #pragma unroll
        for (int q = 0; q < 4; q++) {
            ah[q] = prmt_(ring[slot][q].x, ring[slot][q].y, 0x5410);
            al[q] = prmt_(ring[slot][q].x, ring[slot][q].y, 0x7632);
        }
        if (ks + 2 < 16) {
            int kb = (ks + 2) * 16 + tq * 2;
            ring[slot][0] = *(const uint2*)(g_xpack + (size_t)r0 * Iin + kb);
            ring[slot][1] = *(const uint2*)(g_xpack + (size_t)(r0 + 8) * Iin + kb);
            ring[slot][2] = *(const uint2*)(g_xpack + (size_t)r0 * Iin + kb + 8);
            ring[slot][3] = *(const uint2*)(g_xpack + (size_t)(r0 + 8) * Iin + kb + 8);
        }
        // pass 0: hi*Whi (keep Whi in regs), pass 1: lo*Whi, pass 2: hi*Wlo
        uint32_t bhx[16][2];
        #pragma unroll
        for (int nt = 0; nt < 16; nt++) {
            uint2 vh = *(const uint2*)(sW + ((ks * 16 + nt) * 32 + lane) * 2);
            bhx[nt][0] = vh.x; bhx[nt][1] = vh.y;
            MMA_BF16(acc[nt], ah, vh.x, vh.y);
        }
        #pragma unroll
        for (int nt = 0; nt < 16; nt++)
            MMA_BF16(acc[nt], al, bhx[nt][0], bhx[nt][1]);
        #pragma unroll
        for (int nt = 0; nt < 16; nt++) {
            uint2 vl = *(const uint2*)(sW + 16384 + ((ks * 16 + nt) * 32 + lane) * 2);
            MMA_BF16(acc[nt], ah, vl.x, vl.y);
        }
    }

    #pragma unroll
    for (int nt = 0; nt < 16; nt++) {
        int n = nb * 128 + nt * 8 + tq * 2;
        *(float2*)&g_xp[(size_t)r0 * ND + n] = make_float2(acc[nt][0], acc[nt][1]);
        *(float2*)&g_xp[(size_t)(r0 + 8) * ND + n] = make_float2(acc[nt][2], acc[nt][3]);
    }
}

// ================= persistent mma.sync recurrence =================
// 128 blocks = 64 d-chunks x 2 batch-halves. Block (dn,bh): rows bh*64..+64, N=56.
// Warp w owns 16 rows. 3-pass split bf16, pass-outer (no acc RAW chains).
#define NFRAG 224                 // 32 k-steps * 7 n-tiles
#define PLANE (NFRAG * 64)        // u32 per plane

__global__ __launch_bounds__(NTR, 1)
void recur_kernel(const float* __restrict__ W,
                  const float* __restrict__ dt,
                  const int* __restrict__ sl,
                  float* __restrict__ out_h,
                  float* __restrict__ out_final) {
    extern __shared__ uint32_t sB[];     // [2][NFRAG][32][2]

    const int tid = threadIdx.x;
    const int w = tid >> 5;
    const int lane = tid & 31;
    const int g = lane >> 2;
    const int tq = lane & 3;
    const int dn = blockIdx.x >> 1;
    const int bh = blockIdx.x & 1;
    const int d0 = dn * 8 + tq * 2;

    // ---- pack W h-part fragments into smem (one time) ----
    for (int e = tid; e < NFRAG * 32; e += NTR) {
        int f = e >> 5;
        int l = e & 31;
        int ks = f / 7, nt = f % 7;
        int gg = l >> 2, tt = l & 3;
        int n = nt * Dh + dn * 8 + gg;
        const float* wr = W + (size_t)n * FIN + Iin + ks * 16;
        float w0 = wr[tt * 2], w1 = wr[tt * 2 + 1];
        float w2 = wr[tt * 2 + 8], w3 = wr[tt * 2 + 9];
        __nv_bfloat16 h0 = __float2bfloat16(w0), h1 = __float2bfloat16(w1);
        __nv_bfloat16 h2 = __float2bfloat16(w2), h3 = __float2bfloat16(w3);
        __nv_bfloat16 l0 = __float2bfloat16(w0 - __bfloat162float(h0));
        __nv_bfloat16 l1 = __float2bfloat16(w1 - __bfloat162float(h1));
        __nv_bfloat16 l2 = __float2bfloat16(w2 - __bfloat162float(h2));
        __nv_bfloat16 l3 = __float2bfloat16(w3 - __bfloat162float(h3));
        sB[(f * 32 + l) * 2 + 0] = pack2bf(h0, h1);
        sB[(f * 32 + l) * 2 + 1] = pack2bf(h2, h3);
        sB[PLANE + (f * 32 + l) * 2 + 0] = pack2bf(l0, l1);
        sB[PLANE + (f * 32 + l) * 2 + 1] = pack2bf(l2, l3);
    }

    int rows[2];
    rows[0] = bh * 64 + w * 16 + g;
    rows[1] = rows[0] + 8;
    int lenr[2] = {sl[rows[0]], sl[rows[1]]};

    // ---- init state t=0 ----
    float stC[2][2], stCe[2][2];
    #pragma unroll
    for (int rh = 0; rh < 2; rh++) {
        int b = rows[rh];
        float dtv = dt[b * Lseq + 0];
        float h2v[2];
        uint32_t hp[2];
        #pragma unroll
        for (int cj = 0; cj < 2; cj++) {
            int d = d0 + cj;
            float p0 = g_proj0[0 * Dh + d];
            float p2 = g_proj0[2 * Dh + d];
            float p4 = g_proj0[4 * Dh + d];
            float p5 = g_proj0[5 * Dh + d];
            float p6 = g_proj0[6 * Dh + d];
            float z   = tanhf(p5);
            float cs0 = sigf(p0) * z;
            float ce0 = sigf(p2) * z;
            float o0  = sigf(p4);
            float dn0 = softplusf(p6);
            float c = ce0 + (cs0 - ce0) * expf(-dn0 * dtv);
            float h = o0 * tanhf(c);
            stC[rh][cj] = c;
            stCe[rh][cj] = ce0;
            h2v[cj] = h;
            hp[cj] = pack_hl(h);
        }
        *(float2*)&out_h[((size_t)b * Lseq + 0) * Dh + d0] = make_float2(h2v[0], h2v[1]);
        *(uint2*)&g_Hsplit[0][b * Dh + d0] = make_uint2(hp[0], hp[1]);
    }

    // grid barrier (h_0 visible; xproj finished earlier in-stream)
    unsigned tgt = GRID_R;
    {
        __syncthreads();
        if (tid == 0) {
            red_rel_add1(&g_bar);
            while (ld_acq(&g_bar) < tgt) {}
        }
        __syncthreads();
    }

    // preload XP[0] into acc
    float acc[7][4];
    #pragma unroll
    for (int nt = 0; nt < 7; nt++) {
        float2 x0 = *(const float2*)(g_xp + (size_t)rows[0] * ND + nt * Dh + d0);
        float2 x1 = *(const float2*)(g_xp + (size_t)rows[1] * ND + nt * Dh + d0);
        acc[nt][0] = x0.x; acc[nt][1] = x0.y; acc[nt][2] = x1.x; acc[nt][3] = x1.y;
    }

    for (int t = 0; t < Lseq; t++) {
        const uint32_t* Hs = g_Hsplit[t & 1];

        // ring-4 A prefetch
        uint2 ring[4][4];
        #pragma unroll
        for (int p = 0; p < 4; p++) {
            int kb = p * 16 + tq * 2;
            ring[p][0] = *(const uint2*)(Hs + rows[0] * Dh + kb);
            ring[p][1] = *(const uint2*)(Hs + rows[1] * Dh + kb);
            ring[p][2] = *(const uint2*)(Hs + rows[0] * Dh + kb + 8);
            ring[p][3] = *(const uint2*)(Hs + rows[1] * Dh + kb + 8);
        }

        #pragma unroll 4
        for (int ks = 0; ks < 32; ks++) {
            int slot = ks & 3;
            uint32_t ah[4], al[4];
            #pragma unroll
            for (int q = 0; q < 4; q++) {
                ah[q] = prmt_(ring[slot][q].x, ring[slot][q].y, 0x5410);
                al[q] = prmt_(ring[slot][q].x, ring[slot][q].y, 0x7632);
            }
            if (ks + 4 < 32) {
                int kb = (ks + 4) * 16 + tq * 2;
                ring[slot][0] = *(const uint2*)(Hs + rows[0] * Dh + kb);
                ring[slot][1] = *(const uint2*)(Hs + rows[1] * Dh + kb);
                ring[slot][2] = *(const uint2*)(Hs + rows[0] * Dh + kb + 8);
                ring[slot][3] = *(const uint2*)(Hs + rows[1] * Dh + kb + 8);
            }
            uint32_t bhf[7][2], blf[7][2];
            #pragma unroll
            for (int nt = 0; nt < 7; nt++) {
                const uint32_t* sp = sB + ((ks * 7 + nt) * 32 + lane) * 2;
                uint2 vh = *(const uint2*)sp;
                uint2 vl = *(const uint2*)(sp + PLANE);
                bhf[nt][0] = vh.x; bhf[nt][1] = vh.y;
                blf[nt][0] = vl.x; blf[nt][1] = vl.y;
            }
            // pass-outer: 7 independent accumulators between dependent MMAs
            #pragma unroll
            for (int nt = 0; nt < 7; nt++)
                MMA_BF16(acc[nt], ah, bhf[nt][0], bhf[nt][1]);
            #pragma unroll
            for (int nt = 0; nt < 7; nt++)
                MMA_BF16(acc[nt], al, bhf[nt][0], bhf[nt][1]);
            #pragma unroll
            for (int nt = 0; nt < 7; nt++)
                MMA_BF16(acc[nt], ah, blf[nt][0], blf[nt][1]);
        }

        // ---- epilogue: gates + state ----
        #pragma unroll
        for (int rh = 0; rh < 2; rh++) {
            int b = rows[rh];
            int len = lenr[rh];
            float dtv = 0.0f;
            if (t + 1 < Lseq) dtv = ((t + 1) < len) ? dt[b * Lseq + t + 1] : 0.0f;
            float hn[2];
            uint32_t hp[2];
            #pragma unroll
            for (int cj = 0; cj < 2; cj++) {
                int ci = rh * 2 + cj;
                float i_g  = sigf(acc[0][ci]);
                float f_g  = sigf(acc[1][ci]);
                float ie_g = sigf(acc[2][ci]);
                float fe_g = sigf(acc[3][ci]);
                float o_n  = sigf(acc[4][ci]);
                float z    = tanhf(acc[5][ci]);
                float d_n  = softplusf(acc[6][ci]);
                float cs_n = f_g * stC[rh][cj] + i_g * z;
                float ce_n = fe_g * stCe[rh][cj] + ie_g * z;
                if (t == len - 1) {
                    float* f = out_final + (size_t)b * 4 * Dh + d0 + cj;
                    f[0 * Dh] = o_n;
                    f[1 * Dh] = cs_n;
                    f[2 * Dh] = ce_n;
                    f[3 * Dh] = d_n;
                }
                float cn = ce_n + (cs_n - ce_n) * expf(-d_n * dtv);
                float h = o_n * tanhf(cn);
                stC[rh][cj] = cn;
                stCe[rh][cj] = ce_n;
                hn[cj] = h;
                hp[cj] = pack_hl(h);
            }
            if (t + 1 < Lseq) {
                *(float2*)&out_h[((size_t)b * Lseq + (t + 1)) * Dh + d0] =
                    make_float2(hn[0], hn[1]);
                *(uint2*)&g_Hsplit[(t + 1) & 1][b * Dh + d0] = make_uint2(hp[0], hp[1]);
            }
        }

        if (t + 1 < Lseq) {
            // prefetch XP[t+1] into acc (latency hidden behind barrier wait)
            const float* xpt = g_xp + (size_t)(t + 1) * Bsz * ND;
            #pragma unroll
            for (int nt = 0; nt < 7; nt++) {
                float2 x0 = *(const float2*)(xpt + (size_t)rows[0] * ND + nt * Dh + d0);
                float2 x1 = *(const float2*)(xpt + (size_t)rows[1] * ND + nt * Dh + d0);
                acc[nt][0] = x0.x; acc[nt][1] = x0.y; acc[nt][2] = x1.x; acc[nt][3] = x1.y;
            }
            // grid barrier: h_{t+1} visible before next step's A loads
            tgt += GRID_R;
            __syncthreads();
            if (tid == 0) {
                red_rel_add1(&g_bar);
                while (ld_acq(&g_bar) < tgt) {}
            }
            __syncthreads();
        }
    }
}

// ---------------- launch ----------------
extern "C" void kernel_launch(void* const* d_in, const int* in_sizes, int n_in,
                              void* d_out, int out_size) {
    const float* x    = (const float*)d_in[0];   // (B,L,I)
    const float* dt   = (const float*)d_in[1];   // (B,L)
    const int*   sl   = (const int*)  d_in[2];   // (B,)
    const float* bos  = (const float*)d_in[3];   // (I,)
    const float* W    = (const float*)d_in[4];   // (7D, I+D)
    const float* bias = (const float*)d_in[5];   // (7D,)
    float* out = (float*)d_out;
    float* out_final = out + (size_t)Bsz * Lseq * Dh;

    cudaFuncSetAttribute(recur_kernel, cudaFuncAttributeMaxDynamicSharedMemorySize,
                         2 * PLANE * 4);
    cudaFuncSetAttribute(xproj_hmma_kernel, cudaFuncAttributeMaxDynamicSharedMemorySize,
                         32768 * 4);

    reset_bar_kernel<<<1, 1>>>();
    init_proj_kernel<<<(ND + 255) / 256, 256>>>(bos, W, bias);
    pack_x_kernel<<<(Bsz * Lseq * Iin) / 256, 256>>>(x, sl);
    pack_w_kernel<<<(28 * 16 * 16 * 32 + 255) / 256, 256>>>(W);
    xproj_hmma_kernel<<<dim3(28, 512), 256, 32768 * 4>>>(bias);
    recur_kernel<<<GRID_R, NTR, 2 * PLANE * 4>>>(W, dt, sl, out, out_final);
}

// round 6
// speedup vs baseline: 3.6106x; 1.0000x over previous
#include <cuda_runtime.h>
#include <cuda_bf16.h>
#include <math.h>
#include <stdint.h>

// Problem constants (ContTimeLSTM_66623532695635)
#define Bsz 128
#define Lseq 512
#define Iin 256
#define Dh 512
#define ND 3584          // 7*D
#define FIN 768          // I + D
#define BD (Bsz*Dh)      // 65536

#define GRID_R 128       // persistent recur blocks
#define NTR 256          // 8 warps: wk = w>>2 (k-half), wm = w&3 (row group)

// ---------------- device scratch ----------------
__device__ float g_xp[(size_t)Lseq * Bsz * ND];        // ~940 MB, [t][b][n]
__device__ uint32_t g_Hsplit[2][BD];                   // packed bf16 (hi | lo<<16)
__device__ uint32_t g_xpack[(size_t)Bsz * Lseq * Iin]; // packed masked x
#define WFRAG_PLANE (28 * 16384)
__device__ uint32_t g_wfrag[2 * WFRAG_PLANE];          // W x-part fragments
__device__ float g_proj0[ND];
__device__ unsigned g_bar;

__device__ __forceinline__ float sigf(float x) { return 1.0f / (1.0f + expf(-x)); }
__device__ __forceinline__ float softplusf(float x) {
    return (x > 0.0f) ? (x + log1pf(expf(-x))) : log1pf(expf(x));
}
__device__ __forceinline__ unsigned ld_acq(unsigned* p) {
    unsigned v;
    asm volatile("ld.acquire.gpu.u32 %0, [%1];" : "=r"(v) : "l"(p) : "memory");
    return v;
}
__device__ __forceinline__ void red_rel_add1(unsigned* p) {
    asm volatile("red.release.gpu.global.add.u32 [%0], 1;" :: "l"(p) : "memory");
}
__device__ __forceinline__ uint32_t prmt_(uint32_t a, uint32_t b, uint32_t s) {
    uint32_t r;
    asm("prmt.b32 %0, %1, %2, %3;" : "=r"(r) : "r"(a), "r"(b), "r"(s));
    return r;
}
__device__ __forceinline__ uint32_t pack_hl(float v) {
    __nv_bfloat16 hi = __float2bfloat16(v);
    __nv_bfloat16 lo = __float2bfloat16(v - __bfloat162float(hi));
    return ((uint32_t)__bfloat16_as_ushort(lo) << 16) | __bfloat16_as_ushort(hi);
}
__device__ __forceinline__ uint32_t pack2bf(__nv_bfloat16 a, __nv_bfloat16 b) {
    return ((uint32_t)__bfloat16_as_ushort(b) << 16) | __bfloat16_as_ushort(a);
}

#define MMA_BF16(d, a, b0, b1) \
    asm volatile("mma.sync.aligned.m16n8k16.row.col.f32.bf16.bf16.f32 " \
        "{%0,%1,%2,%3}, {%4,%5,%6,%7}, {%8,%9}, {%0,%1,%2,%3};" \
        : "+f"((d)[0]), "+f"((d)[1]), "+f"((d)[2]), "+f"((d)[3]) \
        : "r"((a)[0]), "r"((a)[1]), "r"((a)[2]), "r"((a)[3]), "r"(b0), "r"(b1))

// ---------------- launch 1: reset barrier + proj0 ----------------
__global__ void prep_kernel(const float* __restrict__ bos,
                            const float* __restrict__ W,
                            const float* __restrict__ bias) {
    int n = blockIdx.x * blockDim.x + threadIdx.x;
    if (n == 0) g_bar = 0u;
    if (n >= ND) return;
    const float* wrow = W + (size_t)n * FIN;
    float acc = bias[n];
    #pragma unroll 8
    for (int i = 0; i < Iin; i++) acc += bos[i] * wrow[i];
    g_proj0[n] = acc;
}

// ---------------- launch 2: pack x (masked) + W x-part fragments ----------------
#define XN (Bsz * Lseq * Iin)          // 16,777,216
#define WN (28 * 16 * 16 * 32)         // 229,376
__global__ void pack_kernel(const float* __restrict__ x,
                            const int* __restrict__ sl,
                            const float* __restrict__ W) {
    int idx = blockIdx.x * blockDim.x + threadIdx.x;
    if (idx < XN) {
        int row = idx >> 8;
        int i = idx & 255;
        int t = row >> 7;
        int b = row & 127;
        float v = (t < __ldg(sl + b)) ? x[((size_t)b * Lseq + t) * Iin + i] : 0.0f;
        g_xpack[idx] = pack_hl(v);
        return;
    }
    int e = idx - XN;
    if (e >= WN) return;
    int lane = e & 31;
    int nt = (e >> 5) & 15;
    int ks = (e >> 9) & 15;
    int nb = e >> 13;
    int gg = lane >> 2, tt = lane & 3;
    int n = nb * 128 + nt * 8 + gg;
    const float* wr = W + (size_t)n * FIN + ks * 16 + tt * 2;
    float w0 = wr[0], w1 = wr[1], w2 = wr[8], w3 = wr[9];
    __nv_bfloat16 h0 = __float2bfloat16(w0), h1 = __float2bfloat16(w1);
    __nv_bfloat16 h2 = __float2bfloat16(w2), h3 = __float2bfloat16(w3);
    __nv_bfloat16 l0 = __float2bfloat16(w0 - __bfloat162float(h0));
    __nv_bfloat16 l1 = __float2bfloat16(w1 - __bfloat162float(h1));
    __nv_bfloat16 l2 = __float2bfloat16(w2 - __bfloat162float(h2));
    __nv_bfloat16 l3 = __float2bfloat16(w3 - __bfloat162float(h3));
    size_t base = (size_t)e * 2;
    g_wfrag[base] = pack2bf(h0, h1);
    g_wfrag[base + 1] = pack2bf(h2, h3);
    g_wfrag[WFRAG_PLANE + base] = pack2bf(l0, l1);
    g_wfrag[WFRAG_PLANE + base + 1] = pack2bf(l2, l3);
}

// ---------------- launch 3: XP = mask(x) @ Wx^T + bias via HMMA ----------------
__global__ __launch_bounds__(256, 1)
void xproj_hmma_kernel(const float* __restrict__ bias) {
    extern __shared__ uint32_t sW[];   // [2][16][16][32][2] = 32768 u32
    const int tid = threadIdx.x;
    const int w = tid >> 5, lane = tid & 31;
    const int g = lane >> 2, tq = lane & 3;
    const int nb = blockIdx.x, mb = blockIdx.y;

    #pragma unroll
    for (int p = 0; p < 2; p++) {
        const uint4* src = (const uint4*)(g_wfrag + (size_t)p * WFRAG_PLANE + nb * 16384);
        uint4* dst = (uint4*)(sW + p * 16384);
        #pragma unroll
        for (int i = 0; i < 16; i++) dst[tid + i * 256] = src[tid + i * 256];
    }
    __syncthreads();

    const int r0 = mb * 128 + w * 16 + g;

    float acc[16][4];
    #pragma unroll
    for (int nt = 0; nt < 16; nt++) {
        int n = nb * 128 + nt * 8 + tq * 2;
        float b0 = __ldg(bias + n), b1 = __ldg(bias + n + 1);
        acc[nt][0] = b0; acc[nt][1] = b1; acc[nt][2] = b0; acc[nt][3] = b1;
    }

    uint2 ring[2][4];
    #pragma unroll
    for (int p = 0; p < 2; p++) {
        int kb = p * 16 + tq * 2;
        ring[p][0] = *(const uint2*)(g_xpack + (size_t)r0 * Iin + kb);
        ring[p][1] = *(const uint2*)(g_xpack + (size_t)(r0 + 8) * Iin + kb);
        ring[p][2] = *(const uint2*)(g_xpack + (size_t)r0 * Iin + kb + 8);
        ring[p][3] = *(const uint2*)(g_xpack + (size_t)(r0 + 8) * Iin + kb + 8);
    }

    #pragma unroll 2
    for (int ks = 0; ks < 16; ks++) {
        int slot = ks & 1;
        uint32_t ah[4], al[4];
        #pragma unroll
        for (int q = 0; q < 4; q++) {
            ah[q] = prmt_(ring[slot][q].x, ring[slot][q].y, 0x5410);
            al[q] = prmt_(ring[slot][q].x, ring[slot][q].y, 0x7632);
        }
        if (ks + 2 < 16) {
            int kb = (ks + 2) * 16 + tq * 2;
            ring[slot][0] = *(const uint2*)(g_xpack + (size_t)r0 * Iin + kb);
            ring[slot][1] = *(const uint2*)(g_xpack + (size_t)(r0 + 8) * Iin + kb);
            ring[slot][2] = *(const uint2*)(g_xpack + (size_t)r0 * Iin + kb + 8);
            ring[slot][3] = *(const uint2*)(g_xpack + (size_t)(r0 + 8) * Iin + kb + 8);
        }
        uint32_t bhx[16][2];
        #pragma unroll
        for (int nt = 0; nt < 16; nt++) {
            uint2 vh = *(const uint2*)(sW + ((ks * 16 + nt) * 32 + lane) * 2);
            bhx[nt][0] = vh.x; bhx[nt][1] = vh.y;
            MMA_BF16(acc[nt], ah, vh.x, vh.y);
        }
        #pragma unroll
        for (int nt = 0; nt < 16; nt++)
            MMA_BF16(acc[nt], al, bhx[nt][0], bhx[nt][1]);
        #pragma unroll
        for (int nt = 0; nt < 16; nt++) {
            uint2 vl = *(const uint2*)(sW + 16384 + ((ks * 16 + nt) * 32 + lane) * 2);
            MMA_BF16(acc[nt], ah, vl.x, vl.y);
        }
    }

    #pragma unroll
    for (int nt = 0; nt < 16; nt++) {
        int n = nb * 128 + nt * 8 + tq * 2;
        *(float2*)&g_xp[(size_t)r0 * ND + n] = make_float2(acc[nt][0], acc[nt][1]);
        *(float2*)&g_xp[(size_t)(r0 + 8) * ND + n] = make_float2(acc[nt][2], acc[nt][3]);
    }
}

// ================= launch 4: persistent recurrence =================
// 128 blocks = 64 d-chunks x 2 batch-halves; 8 warps: split-K (wk) x row-group (wm).
// B-frags interleaved (hi,lo) -> single LDS.128 per (ks,nt).
#define NFRAG 224                    // 32 ks * 7 nt
#define SB_U32 (NFRAG * 32 * 4)      // 28672 u32 = 114688 B
#define SRED_OFF SB_U32              // sRed: 4*32*28 floats = 14336 B

__global__ __launch_bounds__(NTR, 1)
void recur_kernel(const float* __restrict__ W,
                  const float* __restrict__ dt,
                  const int* __restrict__ sl,
                  float* __restrict__ out_h,
                  float* __restrict__ out_final) {
    extern __shared__ uint32_t sB[];
    float* sRed = (float*)(sB + SRED_OFF);

    const int tid = threadIdx.x;
    const int w = tid >> 5;
    const int lane = tid & 31;
    const int g = lane >> 2;
    const int tq = lane & 3;
    const int wm = w & 3;            // row group
    const int wk = w >> 2;           // k-half
    const int dn = blockIdx.x >> 1;
    const int bh = blockIdx.x & 1;
    const int d0 = dn * 8 + tq * 2;

    // ---- pack W h-part fragments (interleaved hi/lo) ----
    for (int e = tid; e < NFRAG * 32; e += NTR) {
        int f = e >> 5;
        int l = e & 31;
        int ks = f / 7, nt = f % 7;
        int gg = l >> 2, tt = l & 3;
        int n = nt * Dh + dn * 8 + gg;
        const float* wr = W + (size_t)n * FIN + Iin + ks * 16;
        float w0 = wr[tt * 2], w1 = wr[tt * 2 + 1];
        float w2 = wr[tt * 2 + 8], w3 = wr[tt * 2 + 9];
        __nv_bfloat16 h0 = __float2bfloat16(w0), h1 = __float2bfloat16(w1);
        __nv_bfloat16 h2 = __float2bfloat16(w2), h3 = __float2bfloat16(w3);
        __nv_bfloat16 l0 = __float2bfloat16(w0 - __bfloat162float(h0));
        __nv_bfloat16 l1 = __float2bfloat16(w1 - __bfloat162float(h1));
        __nv_bfloat16 l2 = __float2bfloat16(w2 - __bfloat162float(h2));
        __nv_bfloat16 l3 = __float2bfloat16(w3 - __bfloat162float(h3));
        uint32_t* p = sB + (size_t)e * 4;
        p[0] = pack2bf(h0, h1);
        p[1] = pack2bf(h2, h3);
        p[2] = pack2bf(l0, l1);
        p[3] = pack2bf(l2, l3);
    }

    int rows[2];
    rows[0] = bh * 64 + wm * 16 + g;
    rows[1] = rows[0] + 8;
    int lenr[2] = {0, 0};
    float stC[2][2], stCe[2][2];

    if (wk == 0) {
        lenr[0] = sl[rows[0]];
        lenr[1] = sl[rows[1]];
        #pragma unroll
        for (int rh = 0; rh < 2; rh++) {
            int b = rows[rh];
            float dtv = dt[b * Lseq + 0];
            float h2v[2];
            uint32_t hp[2];
            #pragma unroll
            for (int cj = 0; cj < 2; cj++) {
                int d = d0 + cj;
                float p0 = g_proj0[0 * Dh + d];
                float p2 = g_proj0[2 * Dh + d];
                float p4 = g_proj0[4 * Dh + d];
                float p5 = g_proj0[5 * Dh + d];
                float p6 = g_proj0[6 * Dh + d];
                float z   = tanhf(p5);
                float cs0 = sigf(p0) * z;
                float ce0 = sigf(p2) * z;
                float o0  = sigf(p4);
                float dn0 = softplusf(p6);
                float c = ce0 + (cs0 - ce0) * expf(-dn0 * dtv);
                float h = o0 * tanhf(c);
                stC[rh][cj] = c;
                stCe[rh][cj] = ce0;
                h2v[cj] = h;
                hp[cj] = pack_hl(h);
            }
            *(float2*)&out_h[((size_t)b * Lseq + 0) * Dh + d0] = make_float2(h2v[0], h2v[1]);
            *(uint2*)&g_Hsplit[0][b * Dh + d0] = make_uint2(hp[0], hp[1]);
        }
    }
    __syncthreads();                 // sB visible block-wide
    if (wk == 0) {
        __syncwarp();
        if (lane == 0) red_rel_add1(&g_bar);
    }
    unsigned tgt = 512;              // 4 arriving warps x 128 blocks
    while (ld_acq(&g_bar) < tgt) {}

    // acc: wk0 = XP[0]; wk1 = 0
    float acc[7][4];
    if (wk == 0) {
        #pragma unroll
        for (int nt = 0; nt < 7; nt++) {
            float2 x0 = *(const float2*)(g_xp + (size_t)rows[0] * ND + nt * Dh + d0);
            float2 x1 = *(const float2*)(g_xp + (size_t)rows[1] * ND + nt * Dh + d0);
            acc[nt][0] = x0.x; acc[nt][1] = x0.y; acc[nt][2] = x1.x; acc[nt][3] = x1.y;
        }
    } else {
        #pragma unroll
        for (int nt = 0; nt < 7; nt++)
            #pragma unroll
            for (int ci = 0; ci < 4; ci++) acc[nt][ci] = 0.0f;
    }

    const int kbase = wk * 256;      // u32 elements (d index) for this k-half

    for (int t = 0; t < Lseq; t++) {
        const uint32_t* Hs = g_Hsplit[t & 1];

        uint2 ring[4][4];
        #pragma unroll
        for (int p = 0; p < 4; p++) {
            int kb = kbase + p * 16 + tq * 2;
            ring[p][0] = *(const uint2*)(Hs + rows[0] * Dh + kb);
            ring[p][1] = *(const uint2*)(Hs + rows[1] * Dh + kb);
            ring[p][2] = *(const uint2*)(Hs + rows[0] * Dh + kb + 8);
            ring[p][3] = *(const uint2*)(Hs + rows[1] * Dh + kb + 8);
        }

        #pragma unroll 4
        for (int ks = 0; ks < 16; ks++) {
            int slot = ks & 3;
            uint32_t ah[4], al[4];
            #pragma unroll
            for (int q = 0; q < 4; q++) {
                ah[q] = prmt_(ring[slot][q].x, ring[slot][q].y, 0x5410);
                al[q] = prmt_(ring[slot][q].x, ring[slot][q].y, 0x7632);
            }
            if (ks + 4 < 16) {
                int kb = kbase + (ks + 4) * 16 + tq * 2;
                ring[slot][0] = *(const uint2*)(Hs + rows[0] * Dh + kb);
                ring[slot][1] = *(const uint2*)(Hs + rows[1] * Dh + kb);
                ring[slot][2] = *(const uint2*)(Hs + rows[0] * Dh + kb + 8);
                ring[slot][3] = *(const uint2*)(Hs + rows[1] * Dh + kb + 8);
            }
            uint4 bv[7];
            #pragma unroll
            for (int nt = 0; nt < 7; nt++)
                bv[nt] = *(const uint4*)(sB + (size_t)(((wk * 16 + ks) * 7 + nt) * 32 + lane) * 4);
            // pass-outer: 7 independent accumulators between dependent MMAs
            #pragma unroll
            for (int nt = 0; nt < 7; nt++)
                MMA_BF16(acc[nt], ah, bv[nt].x, bv[nt].y);
            #pragma unroll
            for (int nt = 0; nt < 7; nt++)
                MMA_BF16(acc[nt], al, bv[nt].x, bv[nt].y);
            #pragma unroll
            for (int nt = 0; nt < 7; nt++)
                MMA_BF16(acc[nt], ah, bv[nt].z, bv[nt].w);
        }

        if (wk == 1) {
            float* rp = sRed + (size_t)(wm * 32 + lane) * 28;
            #pragma unroll
            for (int nt = 0; nt < 7; nt++)
                *(float4*)(rp + nt * 4) =
                    make_float4(acc[nt][0], acc[nt][1], acc[nt][2], acc[nt][3]);
        }
        __syncthreads();

        if (wk == 0) {
            const float4* rp = (const float4*)(sRed + (size_t)(wm * 32 + lane) * 28);
            #pragma unroll
            for (int nt = 0; nt < 7; nt++) {
                float4 r = rp[nt];
                acc[nt][0] += r.x; acc[nt][1] += r.y; acc[nt][2] += r.z; acc[nt][3] += r.w;
            }
            // ---- epilogue: gates + state ----
            #pragma unroll
            for (int rh = 0; rh < 2; rh++) {
                int b = rows[rh];
                int len = lenr[rh];
                float dtv = 0.0f;
                if (t + 1 < Lseq) dtv = ((t + 1) < len) ? dt[b * Lseq + t + 1] : 0.0f;
                float hn[2];
                uint32_t hp[2];
                #pragma unroll
                for (int cj = 0; cj < 2; cj++) {
                    int ci = rh * 2 + cj;
                    float i_g  = sigf(acc[0][ci]);
                    float f_g  = sigf(acc[1][ci]);
                    float ie_g = sigf(acc[2][ci]);
                    float fe_g = sigf(acc[3][ci]);
                    float o_n  = sigf(acc[4][ci]);
                    float z    = tanhf(acc[5][ci]);
                    float d_n  = softplusf(acc[6][ci]);
                    float cs_n = f_g * stC[rh][cj] + i_g * z;
                    float ce_n = fe_g * stCe[rh][cj] + ie_g * z;
                    if (t == len - 1) {
                        float* f = out_final + (size_t)b * 4 * Dh + d0 + cj;
                        f[0 * Dh] = o_n;
                        f[1 * Dh] = cs_n;
                        f[2 * Dh] = ce_n;
                        f[3 * Dh] = d_n;
                    }
                    float cn = ce_n + (cs_n - ce_n) * expf(-d_n * dtv);
                    float h = o_n * tanhf(cn);
                    stC[rh][cj] = cn;
                    stCe[rh][cj] = ce_n;
                    hn[cj] = h;
                    hp[cj] = pack_hl(h);
                }
                if (t + 1 < Lseq) {
                    *(float2*)&out_h[((size_t)b * Lseq + (t + 1)) * Dh + d0] =
                        make_float2(hn[0], hn[1]);
                    *(uint2*)&g_Hsplit[(t + 1) & 1][b * Dh + d0] = make_uint2(hp[0], hp[1]);
                }
            }
            if (t + 1 < Lseq) {
                // prefetch XP[t+1] into acc (hidden behind barrier wait)
                const float* xpt = g_xp + (size_t)(t + 1) * Bsz * ND;
                #pragma unroll
                for (int nt = 0; nt < 7; nt++) {
                    float2 x0 = *(const float2*)(xpt + (size_t)rows[0] * ND + nt * Dh + d0);
                    float2 x1 = *(const float2*)(xpt + (size_t)rows[1] * ND + nt * Dh + d0);
                    acc[nt][0] = x0.x; acc[nt][1] = x0.y;
                    acc[nt][2] = x1.x; acc[nt][3] = x1.y;
                }
                __syncwarp();
                if (lane == 0) red_rel_add1(&g_bar);   // arrival: h_{t+1} published
            }
        } else {
            #pragma unroll
            for (int nt = 0; nt < 7; nt++)
                #pragma unroll
                for (int ci = 0; ci < 4; ci++) acc[nt][ci] = 0.0f;
        }

        tgt += 512;
        if (t + 1 < Lseq) {
            while (ld_acq(&g_bar) < tgt) {}   // all threads poll (warp-coalesced)
        }
    }
}

// ---------------- launch ----------------
extern "C" void kernel_launch(void* const* d_in, const int* in_sizes, int n_in,
                              void* d_out, int out_size) {
    const float* x    = (const float*)d_in[0];   // (B,L,I)
    const float* dt   = (const float*)d_in[1];   // (B,L)
    const int*   sl   = (const int*)  d_in[2];   // (B,)
    const float* bos  = (const float*)d_in[3];   // (I,)
    const float* W    = (const float*)d_in[4];   // (7D, I+D)
    const float* bias = (const float*)d_in[5];   // (7D,)
    float* out = (float*)d_out;
    float* out_final = out + (size_t)Bsz * Lseq * Dh;

    cudaFuncSetAttribute(recur_kernel, cudaFuncAttributeMaxDynamicSharedMemorySize,
                         SB_U32 * 4 + 14336);
    cudaFuncSetAttribute(xproj_hmma_kernel, cudaFuncAttributeMaxDynamicSharedMemorySize,
                         32768 * 4);

    prep_kernel<<<(ND + 255) / 256, 256>>>(bos, W, bias);
    pack_kernel<<<(XN + WN + 255) / 256, 256>>>(x, sl, W);
    xproj_hmma_kernel<<<dim3(28, 512), 256, 32768 * 4>>>(bias);
    recur_kernel<<<GRID_R, NTR, SB_U32 * 4 + 14336>>>(W, dt, sl, out, out_final);
}